// round 13
// baseline (speedup 1.0000x reference)
#include <cuda_runtime.h>
#include <math.h>

// DSimilarity gradgrad, v11 — Chebyshev low-rank, 2-kernel pipeline.
//  k_prep : ONE kernel — phase 1: zero F1/F2 + int-atomic minmax of distances;
//           grid-wide ticket barrier (monotonic counter, replay-safe);
//           phase 2: block 0 computes C (table DCT), blocks 1.. scatter
//           features (16 pairs/block, warp/pair-lane layout, atomicAdd).
//  k_gemm : 128x64x32 tile, 256 thr, 4x8/thread, C-fold fused (unchanged v10).

#define NC     32
#define ROWCAP 2048
#define TSI    128
#define TSJ    64
#define LDA    132
#define LDB    68
#define PPB    16            // pairs per feature block (8 warps x 2)

__device__ float g_F1[ROWCAP * NC];
__device__ float g_F2[ROWCAP * NC];
__device__ float g_C[NC * NC];
__device__ int g_dmin_bits = 0x7F7FFFFF;   // +FLT_MAX (idempotent across replays)
__device__ int g_dmax_bits = 0;            // +0.0f
__device__ unsigned long long g_tick = 0;  // monotonic barrier counter (never reset)

// ------------------------------------------------------------------ prep
__global__ void __launch_bounds__(256, 8) k_prep(
        const float* __restrict__ d1, const float* __restrict__ u1,
        const float* __restrict__ d2, const float* __restrict__ u2,
        const float* __restrict__ ls,
        const int* __restrict__ i1, const int* __restrict__ i2,
        int n1, int n2, int nquads, int nblocks) {
    __shared__ float cosT[128];
    __shared__ float sH[NC][NC + 1];
    __shared__ float sD[NC][NC + 1];

    const int tid  = threadIdx.x;
    const int gtid = blockIdx.x * 256 + tid;
    const int nthr = nblocks * 256;

    // ---------------- phase 1: zero F slices + minmax partials ----------------
    float4 z = make_float4(0.f, 0.f, 0.f, 0.f);
    for (int q = gtid; q < nquads; q += nthr) {
        ((float4*)g_F1)[q] = z;
        ((float4*)g_F2)[q] = z;
    }
    float lo = 3.0e38f, hi = -3.0e38f;
    for (int i = gtid; i < n1; i += nthr) { float v = d1[i]; lo = fminf(lo, v); hi = fmaxf(hi, v); }
    for (int i = gtid; i < n2; i += nthr) { float v = d2[i]; lo = fminf(lo, v); hi = fmaxf(hi, v); }
    #pragma unroll
    for (int d = 16; d > 0; d >>= 1) {
        lo = fminf(lo, __shfl_xor_sync(0xFFFFFFFFu, lo, d));
        hi = fmaxf(hi, __shfl_xor_sync(0xFFFFFFFFu, hi, d));
    }
    if ((tid & 31) == 0) {
        if (lo < 3.0e38f) atomicMin(&g_dmin_bits, __float_as_int(lo));
        if (hi > -3.0e38f) atomicMax(&g_dmax_bits, __float_as_int(hi));
    }

    // ---------------- grid barrier (ticket, monotonic, replay-safe) ----------------
    __syncthreads();
    if (tid == 0) {
        __threadfence();
        unsigned long long ticket = atomicAdd(&g_tick, 1ULL);
        unsigned long long target = ticket - (ticket % (unsigned long long)nblocks)
                                    + (unsigned long long)nblocks;
        volatile unsigned long long* tp = &g_tick;
        while (*tp < target) { }
    }
    __syncthreads();
    __threadfence();

    // ---------------- phase 2 ----------------
    const float lov = __int_as_float(g_dmin_bits);
    const float hiv = __int_as_float(g_dmax_bits);
    const float center = 0.5f * (lov + hiv);
    const float half   = fmaxf(0.5f * (hiv - lov), 1e-6f);

    if (blockIdx.x == 0) {
        // C[32][32]: node grid + table-driven separable DCT
        if (tid < 128) cosT[tid] = cospif(tid / 64.0f);
        __syncthreads();
        const float lsv = ls[0];
        const float invl2 = 1.0f / (lsv * lsv);
        #pragma unroll
        for (int e = tid; e < NC * NC; e += 256) {
            int i = e >> 5, j = e & 31;
            float xi = center + half * cosT[2 * i + 1];
            float yj = center + half * cosT[2 * j + 1];
            float diff = xi - yj;
            float t2 = diff * diff * invl2;
            sH[i][j] = (invl2 - t2 * invl2) * expf(-0.5f * t2);
        }
        __syncthreads();
        #pragma unroll
        for (int e = tid; e < NC * NC; e += 256) {
            int m = e >> 5, j = e & 31;
            float s = 0.0f;
            #pragma unroll
            for (int i = 0; i < NC; i++)
                s = fmaf(sH[i][j], cosT[(m * (2 * i + 1)) & 127], s);
            sD[m][j] = s;
        }
        __syncthreads();
        #pragma unroll
        for (int e = tid; e < NC * NC; e += 256) {
            int m = e >> 5, n = e & 31;
            float s = 0.0f;
            #pragma unroll
            for (int j = 0; j < NC; j++)
                s = fmaf(sD[m][j], cosT[(n * (2 * j + 1)) & 127], s);
            float gm = (m ? 2.0f : 1.0f) * (n ? 2.0f : 1.0f) / (float)(NC * NC);
            g_C[m * NC + n] = s * gm;
        }
        return;
    }

    // feature scatter: 2 pairs per warp, lane = Chebyshev order m
    const int lane = threadIdx.x & 31;
    const int warp = threadIdx.x >> 5;
    #pragma unroll
    for (int rep = 0; rep < 2; rep++) {
        const int w = (blockIdx.x - 1) * PPB + warp + rep * 8;
        if (w < n1) {
            const int p = w;
            float s = (d1[p] - center) / half;
            s = fminf(1.0f, fmaxf(-1.0f, s));
            float th = acosf(s);
            float T = __cosf(lane * th);
            float ux = u1[3 * p], uy = u1[3 * p + 1], uz = u1[3 * p + 2];
            int base = i1[p] * (3 * NC) + lane;
            atomicAdd(&g_F1[base],           ux * T);
            atomicAdd(&g_F1[base + NC],      uy * T);
            atomicAdd(&g_F1[base + 2 * NC],  uz * T);
        } else if (w < n1 + n2) {
            const int q = w - n1;
            float s = (d2[q] - center) / half;
            s = fminf(1.0f, fmaxf(-1.0f, s));
            float th = acosf(s);
            float T = __cosf(lane * th);
            float ux = u2[3 * q], uy = u2[3 * q + 1], uz = u2[3 * q + 2];
            int base = i2[q] * (3 * NC) + lane;
            atomicAdd(&g_F2[base],           ux * T);
            atomicAdd(&g_F2[base + NC],      uy * T);
            atomicAdd(&g_F2[base + 2 * NC],  uz * T);
        }
    }
}

// ------------------------------------------------------------------ GEMM + fold
__global__ void __launch_bounds__(256) k_gemm(float* __restrict__ out,
                                              int nrows, int ncols) {
    __shared__ float As[NC * LDA];       // [k][row 0..127]
    __shared__ float Bs[NC * LDB];       // fold temp [row][32] then [k][row 0..63]
    __shared__ float sC[NC][NC + 1];

    const int t  = threadIdx.x;
    const int Ibase = blockIdx.y * TSI;
    const int Jbase = blockIdx.x * TSJ;

    {
        const int row0 = t >> 5, k = t & 31;
        #pragma unroll
        for (int r = 0; r < 16; r++)
            As[k * LDA + row0 + r * 8] = g_F1[(Ibase + row0 + r * 8) * NC + k];
        #pragma unroll
        for (int r = 0; r < 8; r++)
            Bs[(row0 + r * 8) * NC + k] = g_F2[(Jbase + row0 + r * 8) * NC + k];
        #pragma unroll
        for (int e = t; e < NC * NC; e += 256) sC[e >> 5][e & 31] = g_C[e];
    }
    __syncthreads();

    float hold[8];
    {
        const int k = t & 31, row0 = t >> 5;
        float cr[NC];
        #pragma unroll
        for (int n = 0; n < NC; n++) cr[n] = sC[k][n];
        #pragma unroll
        for (int r = 0; r < 8; r++) {
            const float* f2 = &Bs[(row0 + r * 8) * NC];
            float s = 0.0f;
            #pragma unroll
            for (int n4 = 0; n4 < NC; n4 += 4) {
                float4 v = *(const float4*)&f2[n4];
                s = fmaf(cr[n4],     v.x, s);
                s = fmaf(cr[n4 + 1], v.y, s);
                s = fmaf(cr[n4 + 2], v.z, s);
                s = fmaf(cr[n4 + 3], v.w, s);
            }
            hold[r] = s;
        }
    }
    __syncthreads();
    {
        const int k = t & 31, row0 = t >> 5;
        #pragma unroll
        for (int r = 0; r < 8; r++)
            Bs[k * LDB + row0 + r * 8] = hold[r];
    }
    __syncthreads();

    const int tx = t & 7, ty = t >> 3;
    float acc[4][8] = {};
    #pragma unroll
    for (int k = 0; k < NC; k++) {
        float4 a  = *(const float4*)&As[k * LDA + ty * 4];
        float4 b0 = *(const float4*)&Bs[k * LDB + tx * 8];
        float4 b1 = *(const float4*)&Bs[k * LDB + tx * 8 + 4];
        float av[4] = {a.x, a.y, a.z, a.w};
        float bv[8] = {b0.x, b0.y, b0.z, b0.w, b1.x, b1.y, b1.z, b1.w};
        #pragma unroll
        for (int i = 0; i < 4; i++)
            #pragma unroll
            for (int j = 0; j < 8; j++)
                acc[i][j] = fmaf(av[i], bv[j], acc[i][j]);
    }

    #pragma unroll
    for (int i = 0; i < 4; i++) {
        int I = Ibase + ty * 4 + i;
        if (I >= nrows) break;
        float* orow = out + (size_t)I * ncols;
        #pragma unroll
        for (int j4 = 0; j4 < 8; j4 += 4) {
            int J = Jbase + tx * 8 + j4;
            if (J + 3 < ncols) {
                *(float4*)&orow[J] = make_float4(acc[i][j4], acc[i][j4 + 1],
                                                 acc[i][j4 + 2], acc[i][j4 + 3]);
            } else {
                #pragma unroll
                for (int j = 0; j < 4; j++)
                    if (J + j < ncols) orow[J + j] = acc[i][j4 + j];
            }
        }
    }
}

// ------------------------------------------------------------------ launch
extern "C" void kernel_launch(void* const* d_in, const int* in_sizes, int n_in,
                              void* d_out, int out_size) {
    const float* d1 = (const float*)d_in[0];
    const float* u1 = (const float*)d_in[1];
    const float* d2 = (const float*)d_in[2];
    const float* u2 = (const float*)d_in[3];
    const float* ls = (const float*)d_in[4];
    const int*   i1 = (const int*)d_in[5];
    const int*   i2 = (const int*)d_in[6];
    float* out = (float*)d_out;

    int n1 = in_sizes[0];
    int n2 = in_sizes[2];
    int side = (int)(sqrt((double)out_size) + 0.5);
    int nrows = side, ncols = side;

    int rows_pad = ((side + TSI - 1) / TSI) * TSI;
    if (rows_pad > ROWCAP) rows_pad = ROWCAP;
    int nquads = (rows_pad * NC) / 4;

    int warps = n1 + n2;
    int nblocks = 1 + (warps + PPB - 1) / PPB;   // 1 C-block + feature blocks
    k_prep<<<nblocks, 256>>>(d1, u1, d2, u2, ls, i1, i2, n1, n2, nquads, nblocks);

    dim3 grid((ncols + TSJ - 1) / TSJ, (nrows + TSI - 1) / TSI);
    k_gemm<<<grid, 256>>>(out, nrows, ncols);
}